// round 7
// baseline (speedup 1.0000x reference)
#include <cuda_runtime.h>
#include <cstdint>

// WholeMask R7: max-occupancy store streamer.
// Evidence R1..R6: runtime tracks occupancy only (store-MLP bound); store
// policy and instruction mix are second-order. Design: 256-thr blocks,
// launch_bounds(256,8) -> 2048 thr/SM (regs<=32). Mask padded to 29x29 in
// shared (zero row 28 + zero col 28) so out-of-box = index sentinel: value
// recompute on sy-change is 4 branchless LDS. sx LUT as u8 in shared.
// Row loop reads 4 sy's per LDS.32 and batches 4 independent STG.128s.

#define MH 28
#define MW 28
#define IMG 512
#define MP 29                      // padded tile dim

__global__ __launch_bounds__(256, 8)
void wholemask_kernel(const float* __restrict__ bboxess,
                      const int*   __restrict__ counts,
                      const float* __restrict__ maskss,
                      float*       __restrict__ out,
                      int Kk)
{
    __shared__ float         smask[MP * MP];   // 3364 B, row 28 & col 28 = 0
    __shared__ unsigned char srow[IMG];        // sy per y (28 = zero row)
    __shared__ unsigned char ssx[IMG];         // sx per x (28 = zero col)

    const int slice = blockIdx.x;              // b*K + k
    const int b = slice / Kk;
    const int k = slice - b * Kk;
    const int tid = threadIdx.x;               // 0..255

    const bool valid = (k < counts[b]);

    // Rounded (half-even == jnp.round) + clipped box.
    const float4 bb = reinterpret_cast<const float4*>(bboxess)[slice];
    int y1 = __float2int_rn(bb.x);
    int x1 = __float2int_rn(bb.y);
    int y2 = __float2int_rn(bb.z);
    int x2 = __float2int_rn(bb.w);
    y1 = min(max(y1, 0), IMG - 1);
    x1 = min(max(x1, 0), IMG - 1);
    y2 = min(max(y2, y1 + 1), IMG);
    x2 = min(max(x2, x1 + 1), IMG);
    const int h = y2 - y1;
    const int w = x2 - x1;

    // ---- Setup ----
    {
        // Padded mask tile: zero everything, then fill 28x28 interior.
        const float* gm = maskss + (size_t)slice * (MH * MW);
        for (int i = tid; i < MP * MP; i += 256)
            smask[i] = 0.0f;
        __syncthreads();           // zero-fill before interior writes
        for (int i = tid; i < MH * MW; i += 256)
            smask[(i / MW) * MP + (i % MW)] = gm[i];

        // Per-row sy LUT (sentinel 28) and per-col sx LUT (sentinel 28).
        for (int p = tid; p < IMG; p += 256) {
            const bool iny = valid && (p >= y1) && (p < y2);
            int sy = (p - y1) * MH / h;
            sy = min(max(sy, 0), MH - 1);
            srow[p] = (unsigned char)(iny ? sy : MH);

            const bool inx = (p >= x1) && (p < x2);
            int sx = (p - x1) * MW / w;
            sx = min(max(sx, 0), MW - 1);
            ssx[p] = (unsigned char)(inx ? sx : MW);
        }
    }

    const int lane = tid & 31;
    const int wrp  = tid >> 5;                 // 0..7
    const int q    = wrp & 3;                  // column quarter
    const int band = wrp >> 2;                 // row band 0..1 (16 rows)
    const int x0   = q * 128 + lane * 4;
    __syncthreads();

    // Column offsets for this thread's 4 pixels (u8 loads, then registers).
    const int c0 = ssx[x0];
    const int c1 = ssx[x0 + 1];
    const int c2 = ssx[x0 + 2];
    const int c3 = ssx[x0 + 3];

    // ---- Main: 16 contiguous rows per warp, 4 rows per iteration ----
    const int ybase = blockIdx.y * 32 + band * 16;
    float* op = out + (size_t)slice * (IMG * IMG) + (size_t)ybase * IMG + x0;

    int    prev = -1;
    float4 v = make_float4(0.f, 0.f, 0.f, 0.f);

    #pragma unroll
    for (int r = 0; r < 16; r += 4) {
        const uchar4 s4 = *reinterpret_cast<const uchar4*>(srow + ybase + r);
        const unsigned char sy4[4] = { s4.x, s4.y, s4.z, s4.w };
        #pragma unroll
        for (int j = 0; j < 4; ++j) {
            const int syv = sy4[j];
            if (syv != prev) {                 // warp-uniform, rare
                prev = syv;
                const float* mrow = smask + syv * MP;   // row 28 = zeros
                v.x = mrow[c0];                // col 28 = zeros
                v.y = mrow[c1];
                v.z = mrow[c2];
                v.w = mrow[c3];
            }
            *reinterpret_cast<float4*>(op + (size_t)(r + j) * IMG) = v;
        }
    }
}

extern "C" void kernel_launch(void* const* d_in, const int* in_sizes, int n_in,
                              void* d_out, int out_size)
{
    const float* bboxess = (const float*)d_in[0];   // (B,K,4) f32
    const int*   counts  = (const int*)  d_in[1];   // (B,1)   i32
    const float* maskss  = (const float*)d_in[2];   // (B,K,1,28,28) f32

    const int BK = in_sizes[0] / 4;                 // B*K
    const int Bv = in_sizes[1];                     // B
    const int Kk = BK / Bv;                         // K

    dim3 block(256);
    dim3 grid(BK, IMG / 32);       // 128 slices x 16 chunks = 2048 CTAs
    wholemask_kernel<<<grid, block>>>(bboxess, counts, maskss,
                                      (float*)d_out, Kk);
}